// round 2
// baseline (speedup 1.0000x reference)
#include <cuda_runtime.h>
#include <cuda_bf16.h>
#include <cstdint>

// Problem constants (match reference)
#define NN 100000      // nodes
#define NE 1600000     // edges
#define DD 32          // feature dim
#define NC 8           // float4 chunks per node row (DD/4)

// Ping-pong layer buffers as device globals (no allocation allowed).
// float4 typing guarantees 16B alignment for red.v4.
__device__ float4 g_bufA[NN * NC];
__device__ float4 g_bufB[NN * NC];

// ---------------------------------------------------------------------------
// init: acc(d_out) = x ; bufA = 0
// ---------------------------------------------------------------------------
__global__ void k_init(float4* __restrict__ out, const float4* __restrict__ x,
                       float4* __restrict__ z) {
    int i = blockIdx.x * blockDim.x + threadIdx.x;   // grid sized exactly NN*NC
    out[i] = x[i];
    z[i] = make_float4(0.f, 0.f, 0.f, 0.f);
}

// ---------------------------------------------------------------------------
// SpMM: y[row[e]] += val[e] * h[col[e]]   (COO, 8 lanes per edge, vector red)
// Launched with exactly NE*NC threads (divisible by 256 -> no tail, full warps)
// ---------------------------------------------------------------------------
__global__ void k_spmm(const int* __restrict__ erow, const int* __restrict__ ecol,
                       const float* __restrict__ eval,
                       const float4* __restrict__ h, float4* __restrict__ y) {
    int t = blockIdx.x * blockDim.x + threadIdx.x;
    int e = t >> 3;            // edge index
    int c = t & 7;             // float4 chunk within the 32-wide feature row
    int lane = threadIdx.x & 31;

    int r = 0, cl = 0; float v = 0.f;
    if ((lane & 7) == 0) {     // one load per 8-lane group
        r  = erow[e];
        cl = ecol[e];
        v  = eval[e];
    }
    unsigned src = lane & ~7u; // broadcast within the group
    r  = __shfl_sync(0xffffffffu, r,  src);
    cl = __shfl_sync(0xffffffffu, cl, src);
    v  = __shfl_sync(0xffffffffu, v,  src);

    float4 hv = h[cl * NC + c];            // coalesced 128B line per edge (L2 hit)
    float4 m = make_float4(v * hv.x, v * hv.y, v * hv.z, v * hv.w);

    float4* dst = &y[r * NC + c];
    asm volatile("red.global.add.v4.f32 [%0], {%1, %2, %3, %4};"
                 :: "l"(dst), "f"(m.x), "f"(m.y), "f"(m.z), "f"(m.w)
                 : "memory");
}

// ---------------------------------------------------------------------------
// acc += src ; zero the next ping-pong buffer (fused single pass)
// ---------------------------------------------------------------------------
__global__ void k_acc_zero(float4* __restrict__ acc, const float4* __restrict__ src,
                           float4* __restrict__ z) {
    int i = blockIdx.x * blockDim.x + threadIdx.x;
    float4 a = acc[i], s = src[i];
    acc[i] = make_float4(a.x + s.x, a.y + s.y, a.z + s.z, a.w + s.w);
    z[i] = make_float4(0.f, 0.f, 0.f, 0.f);
}

// ---------------------------------------------------------------------------
// final: acc = (acc + src) * 0.25
// ---------------------------------------------------------------------------
__global__ void k_final(float4* __restrict__ acc, const float4* __restrict__ src) {
    int i = blockIdx.x * blockDim.x + threadIdx.x;
    float4 a = acc[i], s = src[i];
    acc[i] = make_float4((a.x + s.x) * 0.25f, (a.y + s.y) * 0.25f,
                         (a.z + s.z) * 0.25f, (a.w + s.w) * 0.25f);
}

extern "C" void kernel_launch(void* const* d_in, const int* in_sizes, int n_in,
                              void* d_out, int out_size) {
    const int*   erow = (const int*)  d_in[0];
    const int*   ecol = (const int*)  d_in[1];
    const float* eval = (const float*)d_in[2];
    const float4* x   = (const float4*)d_in[3];
    float4* out       = (float4*)d_out;

    float4 *bufA, *bufB;
    cudaGetSymbolAddress((void**)&bufA, g_bufA);
    cudaGetSymbolAddress((void**)&bufB, g_bufB);

    const int nodeThreads = NN * NC;            // 800,000  (=3125 * 256)
    const int edgeThreads = NE * NC;            // 12,800,000 (=50,000 * 256)
    const int nodeBlocks = nodeThreads / 256;
    const int edgeBlocks = edgeThreads / 256;

    // acc = x ; bufA = 0
    k_init<<<nodeBlocks, 256>>>(out, x, bufA);
    // layer 1: bufA = A @ x
    k_spmm<<<edgeBlocks, 256>>>(erow, ecol, eval, x, bufA);
    // acc += bufA ; bufB = 0
    k_acc_zero<<<nodeBlocks, 256>>>(out, bufA, bufB);
    // layer 2: bufB = A @ bufA
    k_spmm<<<edgeBlocks, 256>>>(erow, ecol, eval, bufA, bufB);
    // acc += bufB ; bufA = 0
    k_acc_zero<<<nodeBlocks, 256>>>(out, bufB, bufA);
    // layer 3: bufA = A @ bufB
    k_spmm<<<edgeBlocks, 256>>>(erow, ecol, eval, bufB, bufA);
    // acc = (acc + bufA) / 4
    k_final<<<nodeBlocks, 256>>>(out, bufA);
}